// round 1
// baseline (speedup 1.0000x reference)
#include <cuda_runtime.h>
#include <cuda_bf16.h>

// ---------------------------------------------------------------------------
// DetectionLoss (YOLOv5-style) for shapes:
//   p3 [16,3,80,80,85] p4 [16,3,40,40,85] p5 [16,3,20,20,85]
//   boxes [16,64,4] xyxy, labels [16,64] i32, valid [16,64] bool, anchors [3,3,2]
// Output: scalar f32.
//
// Math reduction:
//   BCE(x,t) = softplus(x) - x*t   (t in {0,1})
//   obj loss per layer = ( sum_all softplus(x4)  -  sum_{unique pos cells} x4 ) / Ncells
// cls/bbox losses are gathers over <=1024 candidate boxes per layer.
// ---------------------------------------------------------------------------

#define B_   16
#define M_   64
#define A_   3
#define NC_  80
#define CH_  85
#define NBOX (B_ * M_)            // 1024
#define CELLS0 (B_ * A_ * 80 * 80)   // 307200
#define CELLS1 (B_ * A_ * 40 * 40)   // 76800
#define CELLS2 (B_ * A_ * 20 * 20)   // 19200
#define CELLS_TOTAL (CELLS0 + CELLS1 + CELLS2)  // 403200

static __device__ double g_sp[3];      // sum softplus(x4) over whole grid
static __device__ float  g_negx[3];    // - sum x4 over unique positive cells
static __device__ float  g_cls[3];
static __device__ float  g_box[3];
static __device__ int    g_npos[3];
static __device__ int    g_flags[CELLS_TOTAL];   // dedup flags (zeroed each launch)

__device__ __forceinline__ float softplusf(float x) {
    return fmaxf(x, 0.0f) + log1pf(expf(-fabsf(x)));
}

// ---------------------------------------------------------------------------
__global__ void dl_zero_kernel() {
    int i = blockIdx.x * blockDim.x + threadIdx.x;
    if (i < CELLS_TOTAL) g_flags[i] = 0;
    if (i < 3) {
        g_sp[i] = 0.0;
        g_negx[i] = 0.0f;
        g_cls[i]  = 0.0f;
        g_box[i]  = 0.0f;
        g_npos[i] = 0;
    }
}

// ---------------------------------------------------------------------------
// One block per layer, one thread per candidate box (B*M = 1024).
__global__ void dl_pos_kernel(const float* __restrict__ p3,
                              const float* __restrict__ p4,
                              const float* __restrict__ p5,
                              const float* __restrict__ boxes,
                              const int*   __restrict__ labels,
                              const unsigned char* __restrict__ valid,
                              const float* __restrict__ anchors) {
    const int layer = blockIdx.x;       // 0..2
    const int i     = threadIdx.x;      // 0..1023  (flat b*M + m)
    const int b     = i >> 6;           // /64
    const int g     = 80 >> layer;      // 80,40,20

    const float* P = (layer == 0) ? p3 : (layer == 1) ? p4 : p5;
    const int loff = (layer == 0) ? 0 : (layer == 1) ? CELLS0 : (CELLS0 + CELLS1);

    const float x1 = boxes[i * 4 + 0];
    const float y1 = boxes[i * 4 + 1];
    const float x2 = boxes[i * 4 + 2];
    const float y2 = boxes[i * 4 + 3];
    const float gf = (float)g;
    const float cx = (x1 + x2) * 0.5f * gf;
    const float cy = (y1 + y2) * 0.5f * gf;
    const float w  = (x2 - x1) * gf;
    const float h  = (y2 - y1) * gf;

    // wh-only IoU vs this layer's 3 anchors; argmax = first max (strict >)
    float best = -1.0f;
    int   ba   = 0;
#pragma unroll
    for (int a = 0; a < A_; a++) {
        const float aw = anchors[layer * 6 + a * 2 + 0];
        const float ah = anchors[layer * 6 + a * 2 + 1];
        const float inter = fminf(w, aw) * fminf(h, ah);
        const float uni   = w * h + aw * ah - inter;
        const float iou   = inter / (uni + 1e-6f);
        if (iou > best) { best = iou; ba = a; }
    }

    if (!valid[i] || !(best > 0.5f)) return;   // strict threshold, valid mask

    int gx = (int)cx; gx = min(max(gx, 0), g - 1);
    int gy = (int)cy; gy = min(max(gy, 0), g - 1);

    const int  cellInLayer = ((b * A_ + ba) * g + gy) * g + gx;
    const long base        = (long)cellInLayer * CH_;

    atomicAdd(&g_npos[layer], 1);

    // ---- cls: sum_c softplus(x_c) - x_label -------------------------------
    const int lab = labels[i];
    float cl = 0.0f;
#pragma unroll 4
    for (int c = 0; c < NC_; c++) {
        cl += softplusf(__ldg(&P[base + 5 + c]));
    }
    cl -= __ldg(&P[base + 5 + lab]);
    atomicAdd(&g_cls[layer], cl);

    // ---- bbox: CIoU-style loss (matches reference epsilons) ---------------
    const float pcx0 = P[base + 0], pcy0 = P[base + 1];
    const float pw   = P[base + 2], ph   = P[base + 3];
    const float px1 = pcx0 - pw * 0.5f, py1 = pcy0 - ph * 0.5f;
    const float px2 = pcx0 + pw * 0.5f, py2 = pcy0 + ph * 0.5f;
    const float tx1 = cx - w * 0.5f, ty1 = cy - h * 0.5f;
    const float tx2 = cx + w * 0.5f, ty2 = cy + h * 0.5f;

    const float ix1 = fmaxf(px1, tx1), iy1 = fmaxf(py1, ty1);
    const float ix2 = fminf(px2, tx2), iy2 = fminf(py2, ty2);
    const float inter = fmaxf(ix2 - ix1, 0.0f) * fmaxf(iy2 - iy1, 0.0f);
    const float a1 = (px2 - px1) * (py2 - py1);
    const float a2 = (tx2 - tx1) * (ty2 - ty1);
    const float iou = inter / (a1 + a2 - inter + 1e-7f);

    const float pcx = (px1 + px2) * 0.5f, pcy = (py1 + py2) * 0.5f;
    const float tcx = (tx1 + tx2) * 0.5f, tcy = (ty1 + ty2) * 0.5f;
    const float cd  = (pcx - tcx) * (pcx - tcx) + (pcy - tcy) * (pcy - tcy);

    const float ex1 = fminf(px1, tx1), ey1 = fminf(py1, ty1);
    const float ex2 = fmaxf(px2, tx2), ey2 = fmaxf(py2, ty2);
    const float dd  = (ex2 - ex1) * (ex2 - ex1) + (ey2 - ey1) * (ey2 - ey1);

    const float closs = 1.0f - (iou - cd / (dd + 1e-7f));
    atomicAdd(&g_box[layer], closs);

    // ---- obj correction on UNIQUE cells (scatter-max dedup) ---------------
    if (atomicExch(&g_flags[loff + cellInLayer], 1) == 0) {
        atomicAdd(&g_negx[layer], -P[base + 4]);
    }
}

// ---------------------------------------------------------------------------
// Sum softplus(pred[...,4]) over every cell. grid = (1200, 3) x 256.
__global__ void dl_obj_kernel(const float* __restrict__ p3,
                              const float* __restrict__ p4,
                              const float* __restrict__ p5) {
    const int layer = blockIdx.y;
    const int ncell = CELLS0 >> (2 * layer);   // 307200, 76800, 19200
    const float* P = (layer == 0) ? p3 : (layer == 1) ? p4 : p5;

    const int idx = blockIdx.x * blockDim.x + threadIdx.x;
    float v = 0.0f;
    if (idx < ncell) v = softplusf(__ldg(&P[(long)idx * CH_ + 4]));

    __shared__ float sm[256];
    sm[threadIdx.x] = v;
    __syncthreads();
#pragma unroll
    for (int s = 128; s > 0; s >>= 1) {
        if (threadIdx.x < s) sm[threadIdx.x] += sm[threadIdx.x + s];
        __syncthreads();
    }
    if (threadIdx.x == 0 && sm[0] != 0.0f) atomicAdd(&g_sp[layer], (double)sm[0]);
}

// ---------------------------------------------------------------------------
__global__ void dl_fin_kernel(float* __restrict__ out) {
    double cls = 0.0, obj = 0.0, box = 0.0;
    const double ncell[3] = {(double)CELLS0, (double)CELLS1, (double)CELLS2};
#pragma unroll
    for (int l = 0; l < 3; l++) {
        const float np = (float)g_npos[l];
        if (np > 0.0f) {                    // has-positives gate per layer
            const float denom = fmaxf(np, 1.0f);
            cls += (double)g_cls[l] / ((double)denom * (double)NC_);
            obj += (g_sp[l] + (double)g_negx[l]) / ncell[l];
            box += (double)g_box[l] / (double)denom;
        }
    }
    out[0] = (float)(0.5 * cls + 1.0 * obj + 0.05 * box);
}

// ---------------------------------------------------------------------------
extern "C" void kernel_launch(void* const* d_in, const int* in_sizes, int n_in,
                              void* d_out, int out_size) {
    const float*         p3      = (const float*)d_in[0];
    const float*         p4      = (const float*)d_in[1];
    const float*         p5      = (const float*)d_in[2];
    const float*         boxes   = (const float*)d_in[3];
    const int*           labels  = (const int*)d_in[4];
    const unsigned char* valid   = (const unsigned char*)d_in[5];
    const float*         anchors = (const float*)d_in[6];
    float*               out     = (float*)d_out;

    dl_zero_kernel<<<(CELLS_TOTAL + 255) / 256, 256>>>();
    dl_pos_kernel<<<3, NBOX>>>(p3, p4, p5, boxes, labels, valid, anchors);
    dl_obj_kernel<<<dim3((CELLS0 + 255) / 256, 3), 256>>>(p3, p4, p5);
    dl_fin_kernel<<<1, 1>>>(out);
}